// round 7
// baseline (speedup 1.0000x reference)
#include <cuda_runtime.h>

__device__ __forceinline__ float4 vqc_one(float4 e0, float4 e1, float4 e2,
                                          float4 n0, float4 n1, float4 n2) {
    float t[12] = {e0.x, e0.y, e0.z, e0.w,
                   e1.x, e1.y, e1.z, e1.w,
                   e2.x, e2.y, e2.z, e2.w};
    float x[4], y[4], z[4];
#pragma unroll
    for (int q = 0; q < 4; q++) {
        float s0, c0, s1, c1, s2, c2;
        __sincosf(t[3 * q + 0], &s0, &c0);
        __sincosf(t[3 * q + 1], &s1, &c1);
        __sincosf(t[3 * q + 2], &s2, &c2);
        float cc = c0 * c1;
        x[q] = cc * c2 - s0 * s2;
        y[q] = cc * s2 + s0 * c2;
        z[q] = -c0 * s1;
    }
    float z01   = z[0] * z[1];
    float z23   = z[2] * z[3];
    float z012  = z01 * z[2];
    float z123  = z[1] * z23;
    float z0123 = z01 * z23;
    float x01   = x[0] * x[1];

    float4 o;
    o.x = n0.x * x01           + n0.y * (x[0] * y[1] * z23)         + n0.z * z123;
    o.y = n0.w * (x[1] * x[2]) + n1.x * (z[0] * y[1] * x[2])        + n1.y * z01;
    o.z = n1.z * (x[2] * x[3]) + n1.w * (z01 * y[2] * x[3])         + n2.x * z012;
    o.w = n2.y * (x01 * x[3])  - n2.z * (y[0] * y[1] * z[2] * y[3]) + n2.w * z0123;
    return o;
}

// Per-warp tile = 32 items = 96 float4 = 1536 B, loaded as 3 coalesced LDG.128.
__global__ __launch_bounds__(256, 5) void vqc_fused(const float4* __restrict__ enc,
                                                    const float* __restrict__ w,
                                                    float4* __restrict__ out,
                                                    int B) {
    // Observable coefficients from shared weights (cheap, per block).
    __shared__ __align__(16) float sn[12];
    if (threadIdx.x < 4) {
        int q = threadIdx.x;
        float st, ct, sl, cl;
        __sincosf(w[q * 3 + 0], &st, &ct);
        __sincosf(w[q * 3 + 2], &sl, &cl);
        sn[q * 3 + 0] = -st * cl;
        sn[q * 3 + 1] =  st * sl;
        sn[q * 3 + 2] =  ct;
    }
    // Per-warp double-buffered transpose staging: [warp][stage][component][item].
    __shared__ float4 sbuf[8][2][3][32];
    __syncthreads();

    const float4* n4 = (const float4*)sn;
    const float4 n0 = n4[0], n1 = n4[1], n2 = n4[2];

    const int lane = threadIdx.x & 31;
    const int wid  = threadIdx.x >> 5;
    const int nvec = B * 3;                       // total float4s in enc
    const int tiles = (B + 31) >> 5;              // 32-item tiles
    const int wstride = gridDim.x * 8;            // warps in grid

    int g = blockIdx.x * 8 + wid;                 // this warp's first tile
    if (g >= tiles) return;

    // Prime: coalesced load of tile g.
    float4 r0, r1, r2;
    {
        int vb = g * 96;
        r0 = (vb +      lane < nvec) ? __ldcs(enc + vb +      lane) : make_float4(0,0,0,0);
        r1 = (vb + 32 + lane < nvec) ? __ldcs(enc + vb + 32 + lane) : make_float4(0,0,0,0);
        r2 = (vb + 64 + lane < nvec) ? __ldcs(enc + vb + 64 + lane) : make_float4(0,0,0,0);
    }

    int p = 0;
    while (true) {
        // Scatter loaded tile into component planes: local v = k*32+lane,
        // item m = v/3, component j = v%3.  (<=2-way STS conflicts)
        {
            int v0 = lane;          sbuf[wid][p][v0 % 3][v0 / 3] = r0;
            int v1 = 32 + lane;     sbuf[wid][p][v1 % 3][v1 / 3] = r1;
            int v2 = 64 + lane;     sbuf[wid][p][v2 % 3][v2 / 3] = r2;
        }
        __syncwarp();

        // Issue next tile's coalesced loads NOW — in flight during compute.
        int g2 = g + wstride;
        if (g2 < tiles) {
            int vb = g2 * 96;
            r0 = (vb +      lane < nvec) ? __ldcs(enc + vb +      lane) : make_float4(0,0,0,0);
            r1 = (vb + 32 + lane < nvec) ? __ldcs(enc + vb + 32 + lane) : make_float4(0,0,0,0);
            r2 = (vb + 64 + lane < nvec) ? __ldcs(enc + vb + 64 + lane) : make_float4(0,0,0,0);
        }

        // Conflict-free gather: this thread's 12 angles.
        float4 e0 = sbuf[wid][p][0][lane];
        float4 e1 = sbuf[wid][p][1][lane];
        float4 e2 = sbuf[wid][p][2][lane];

        int item = g * 32 + lane;
        if (item < B) {
            float4 o = vqc_one(e0, e1, e2, n0, n1, n2);
            __stcs(&out[item], o);   // coalesced STG.128, write-once stream
        }

        if (g2 >= tiles) break;
        g = g2;
        p ^= 1;
    }
}

extern "C" void kernel_launch(void* const* d_in, const int* in_sizes, int n_in,
                              void* d_out, int out_size) {
    int ei = 0, wi = 1;
    if (n_in >= 2 && in_sizes[0] < in_sizes[1]) { ei = 1; wi = 0; }
    const float* enc = (const float*)d_in[ei];
    const float* w   = (const float*)d_in[wi];
    int B = in_sizes[ei] / 12;

    const int threads = 256;
    int tiles = (B + 31) / 32;
    int need = (tiles + 7) / 8;          // blocks if each warp took one tile
    int max_blocks = 152 * 5;            // one resident wave at 5 blocks/SM
    int blocks = need < max_blocks ? need : max_blocks;

    vqc_fused<<<blocks, threads>>>((const float4*)enc, w, (float4*)d_out, B);
}

// round 8
// speedup vs baseline: 1.3145x; 1.3145x over previous
#include <cuda_runtime.h>

// FMA-pipe sincos: 2*pi range reduction + Taylor deg-13 (sin) / deg-14 (cos).
// Valid to ~2e-5 abs over all |r|<=pi; inputs here are N(0,1) so k in {-1,0,1}.
__device__ __forceinline__ void sincos_poly(float t, float& s, float& c) {
    float k = rintf(t * 0.15915494309189535f);
    float r = fmaf(k, -6.28125f, t);
    r = fmaf(k, -0.0019353071795864769f, r);
    float r2 = r * r;
    // sin(r) = r * P(r2)
    float ps = fmaf(r2, 1.6059044e-10f, -2.5052108e-8f);
    ps = fmaf(r2, ps, 2.7557319e-6f);
    ps = fmaf(r2, ps, -1.9841270e-4f);
    ps = fmaf(r2, ps, 8.3333333e-3f);
    ps = fmaf(r2, ps, -1.6666667e-1f);
    s = r * fmaf(r2, ps, 1.0f);
    // cos(r) = Q(r2)
    float pc = fmaf(r2, -1.1470746e-11f, 2.0876757e-9f);
    pc = fmaf(r2, pc, -2.7557319e-7f);
    pc = fmaf(r2, pc, 2.4801587e-5f);
    pc = fmaf(r2, pc, -1.3888889e-3f);
    pc = fmaf(r2, pc, 4.1666667e-2f);
    pc = fmaf(r2, pc, -0.5f);
    c = fmaf(r2, pc, 1.0f);
}

__device__ __forceinline__ float4 vqc_one(float4 e0, float4 e1, float4 e2,
                                          float4 n0, float4 n1, float4 n2) {
    float t[12] = {e0.x, e0.y, e0.z, e0.w,
                   e1.x, e1.y, e1.z, e1.w,
                   e2.x, e2.y, e2.z, e2.w};
    float x[4], y[4], z[4];
#pragma unroll
    for (int q = 0; q < 4; q++) {
        float s0, c0, s1, c1, s2, c2;
        // Rebalance: angles t[1] (q0,Ry) and t[7] (q2,Ry) go to the FMA pipe;
        // the other 10 stay on MUFU. MUFU: 24 -> 20 ops/item.
        __sincosf(t[3 * q + 0], &s0, &c0);
        if (q == 0 || q == 2) sincos_poly(t[3 * q + 1], s1, c1);
        else                  __sincosf(t[3 * q + 1], &s1, &c1);
        __sincosf(t[3 * q + 2], &s2, &c2);
        float cc = c0 * c1;
        x[q] = cc * c2 - s0 * s2;
        y[q] = cc * s2 + s0 * c2;
        z[q] = -c0 * s1;
    }
    float z01   = z[0] * z[1];
    float z23   = z[2] * z[3];
    float z012  = z01 * z[2];
    float z123  = z[1] * z23;
    float z0123 = z01 * z23;
    float x01   = x[0] * x[1];

    float4 o;
    o.x = n0.x * x01           + n0.y * (x[0] * y[1] * z23)         + n0.z * z123;
    o.y = n0.w * (x[1] * x[2]) + n1.x * (z[0] * y[1] * x[2])        + n1.y * z01;
    o.z = n1.z * (x[2] * x[3]) + n1.w * (z01 * y[2] * x[3])         + n2.x * z012;
    o.w = n2.y * (x01 * x[3])  - n2.z * (y[0] * y[1] * z[2] * y[3]) + n2.w * z0123;
    return o;
}

__global__ __launch_bounds__(256) void vqc_fused(const float4* __restrict__ enc,
                                                 const float* __restrict__ w,
                                                 float4* __restrict__ out,
                                                 int B) {
    __shared__ __align__(16) float sn[12];
    if (threadIdx.x < 4) {
        int q = threadIdx.x;
        float st, ct, sl, cl;
        __sincosf(w[q * 3 + 0], &st, &ct);
        __sincosf(w[q * 3 + 2], &sl, &cl);
        sn[q * 3 + 0] = -st * cl;
        sn[q * 3 + 1] =  st * sl;
        sn[q * 3 + 2] =  ct;
    }
    __syncthreads();
    const float4* n4 = (const float4*)sn;
    float4 n0 = n4[0], n1 = n4[1], n2 = n4[2];

    const int stride = gridDim.x * blockDim.x;
    int i = blockIdx.x * blockDim.x + threadIdx.x;

    for (; i < B; i += stride) {
        const float4* p = enc + 3 * i;
        float4 e0 = __ldcs(p + 0);
        float4 e1 = __ldcs(p + 1);
        float4 e2 = __ldcs(p + 2);
        float4 o = vqc_one(e0, e1, e2, n0, n1, n2);
        __stcs(&out[i], o);
    }
}

extern "C" void kernel_launch(void* const* d_in, const int* in_sizes, int n_in,
                              void* d_out, int out_size) {
    int ei = 0, wi = 1;
    if (n_in >= 2 && in_sizes[0] < in_sizes[1]) { ei = 1; wi = 0; }
    const float* enc = (const float*)d_in[ei];
    const float* w   = (const float*)d_in[wi];
    int B = in_sizes[ei] / 12;

    const int threads = 256;
    int max_blocks = 152 * 8;
    int need = (B + threads - 1) / threads;
    int blocks = need < max_blocks ? need : max_blocks;

    vqc_fused<<<blocks, threads>>>((const float4*)enc, w, (float4*)d_out, B);
}